// round 3
// baseline (speedup 1.0000x reference)
#include <cuda_runtime.h>
#include <cstdint>

// ---------------------------------------------------------------------------
// RSSM observe scan, GB300.
// Structure:
//   k_pre_inp : pre_inp[t,b,:] = b_inp + ctx@Winp[30:260] + act@Winp[260:292]
//   k_pre_obs : pre_obs[t,b,:] = b_obs + embed@Wobs[200:1224]
//   k_rssm    : 128 CTAs x 4 rows each, 64 sequential steps, no inter-CTA sync.
// All fp32; inner products use packed fma.rn.f32x2 (rows paired in 64-bit regs).
// ---------------------------------------------------------------------------

#define Bc 512
#define Tc 64
#define Ec 1024
#define Ac 32
#define Sc 30
#define Dc 200
#define Hc 200
#define SSc 230
#define OUTC 380

typedef unsigned long long ull;

// scratch (allocation-free): [T, B, H]
__device__ float g_pre_inp[Tc * Bc * Hc];
__device__ float g_pre_obs[Tc * Bc * Hc];

// ---- packed f32x2 helpers -------------------------------------------------
__device__ __forceinline__ ull pk2(float a, float b) {
    ull r; asm("mov.b64 %0, {%1, %2};" : "=l"(r) : "f"(a), "f"(b)); return r;
}
__device__ __forceinline__ ull dup2(float a) {
    ull r; asm("mov.b64 %0, {%1, %1};" : "=l"(r) : "f"(a)); return r;
}
__device__ __forceinline__ float2 up2(ull v) {
    float x, y; asm("mov.b64 {%0, %1}, %2;" : "=f"(x), "=f"(y) : "l"(v));
    return make_float2(x, y);
}
__device__ __forceinline__ void fma2(ull& acc, ull a, ull b) {
    asm("fma.rn.f32x2 %0, %1, %2, %0;" : "+l"(acc) : "l"(a), "l"(b));
}

// ---- activations ------------------------------------------------------------
__device__ __forceinline__ float sigm(float x) { return 1.0f / (1.0f + __expf(-x)); }
__device__ __forceinline__ float eluf(float x) { return x > 0.0f ? x : expm1f(x); }
__device__ __forceinline__ float softplusf(float x) {
    return x > 15.0f ? x : log1pf(__expf(x));
}

// ===========================================================================
// k_pre_obs: [32768, 1024] x [1024, 200]  (weight rows 200..1223 of w_obs_out)
// block = 128 thr = (32 col-pairs, 4 row-groups); tile 64 rows x 64 cols;
// each thread: 8 row-pairs x 2 cols (16 outputs), rows packed in f32x2.
// ===========================================================================
__global__ void __launch_bounds__(128) k_pre_obs(const float* __restrict__ embed,
                                                 const float* __restrict__ w_obs,
                                                 const float* __restrict__ b_obs) {
    __shared__ __align__(8) float As[16][66];
    const int tid = threadIdx.x;
    const int jp = tid & 31, rg = tid >> 5;
    const int row0 = blockIdx.x * 64;
    const int j0 = blockIdx.y * 64 + jp * 2;
    const bool act = (j0 < Hc);
    const int rbase = rg * 16;

    ull acc[16];
#pragma unroll
    for (int i = 0; i < 16; i++) acc[i] = 0ull;

    for (int k0 = 0; k0 < Ec; k0 += 16) {
#pragma unroll
        for (int i = 0; i < 8; i++) {
            int lin = tid + i * 128;
            int kk = lin & 15, r = lin >> 4;
            int rowg = row0 + r;            // rowg = t*B + b
            int tt = rowg >> 9, bb = rowg & 511;
            As[kk][r] = embed[(size_t)(bb * Tc + tt) * Ec + k0 + kk];
        }
        __syncthreads();
        if (act) {
#pragma unroll
            for (int kk = 0; kk < 16; kk++) {
                float2 w = *reinterpret_cast<const float2*>(
                    w_obs + (size_t)(Dc + k0 + kk) * Hc + j0);
                ull wx = dup2(w.x), wy = dup2(w.y);
                const ull* ap = reinterpret_cast<const ull*>(&As[kk][rbase]);
#pragma unroll
                for (int p = 0; p < 8; p++) {
                    ull a = ap[p];
                    fma2(acc[2 * p], a, wx);
                    fma2(acc[2 * p + 1], a, wy);
                }
            }
        }
        __syncthreads();
    }
    if (act) {
        float bx = b_obs[j0], by = b_obs[j0 + 1];
#pragma unroll
        for (int p = 0; p < 8; p++) {
            float2 va = up2(acc[2 * p]), vb = up2(acc[2 * p + 1]);
            int r = row0 + rbase + 2 * p;
            *reinterpret_cast<float2*>(g_pre_obs + (size_t)r * Hc + j0) =
                make_float2(va.x + bx, vb.x + by);
            *reinterpret_cast<float2*>(g_pre_obs + (size_t)(r + 1) * Hc + j0) =
                make_float2(va.y + bx, vb.y + by);
        }
    }
}

// ===========================================================================
// k_pre_inp: [32768, 262] x [262, 200]; K piecewise = ctx(230) ++ act(32),
// weight rows 30..291 of w_inp. Same tiling as k_pre_obs. K padded to 272.
// ===========================================================================
__global__ void __launch_bounds__(128) k_pre_inp(const float* __restrict__ ctx,
                                                 const float* __restrict__ actn,
                                                 const float* __restrict__ w_inp,
                                                 const float* __restrict__ b_inp) {
    __shared__ __align__(8) float As[16][66];
    const int tid = threadIdx.x;
    const int jp = tid & 31, rg = tid >> 5;
    const int row0 = blockIdx.x * 64;
    const int j0 = blockIdx.y * 64 + jp * 2;
    const bool act = (j0 < Hc);
    const int rbase = rg * 16;

    ull acc[16];
#pragma unroll
    for (int i = 0; i < 16; i++) acc[i] = 0ull;

    for (int k0 = 0; k0 < 272; k0 += 16) {
#pragma unroll
        for (int i = 0; i < 8; i++) {
            int lin = tid + i * 128;
            int kk = lin & 15, r = lin >> 4;
            int rowg = row0 + r;
            int tt = rowg >> 9, bb = rowg & 511;
            int k = k0 + kk;
            float v = 0.0f;
            if (k < SSc)            v = ctx[(size_t)(bb * Tc + tt) * SSc + k];
            else if (k < SSc + Ac)  v = actn[(size_t)(bb * Tc + tt) * Ac + (k - SSc)];
            As[kk][r] = v;
        }
        __syncthreads();
        if (act) {
#pragma unroll
            for (int kk = 0; kk < 16; kk++) {
                int kw = (k0 + kk < SSc + Ac) ? (k0 + kk) : (SSc + Ac - 1); // clamp; As=0 there
                float2 w = *reinterpret_cast<const float2*>(
                    w_inp + (size_t)(Sc + kw) * Hc + j0);
                ull wx = dup2(w.x), wy = dup2(w.y);
                const ull* ap = reinterpret_cast<const ull*>(&As[kk][rbase]);
#pragma unroll
                for (int p = 0; p < 8; p++) {
                    ull a = ap[p];
                    fma2(acc[2 * p], a, wx);
                    fma2(acc[2 * p + 1], a, wy);
                }
            }
        }
        __syncthreads();
    }
    if (act) {
        float bx = b_inp[j0], by = b_inp[j0 + 1];
#pragma unroll
        for (int p = 0; p < 8; p++) {
            float2 va = up2(acc[2 * p]), vb = up2(acc[2 * p + 1]);
            int r = row0 + rbase + 2 * p;
            *reinterpret_cast<float2*>(g_pre_inp + (size_t)r * Hc + j0) =
                make_float2(va.x + bx, vb.x + by);
            *reinterpret_cast<float2*>(g_pre_inp + (size_t)(r + 1) * Hc + j0) =
                make_float2(va.y + bx, vb.y + by);
        }
    }
}

// ===========================================================================
// k_rssm: the sequential scan. 128 CTAs x 256 threads; CTA owns 4 batch rows.
// All activations live in smem packed as float[ j ][ 4 rows ] (row-pairs are
// 8-byte aligned -> f32x2 math against a duplicated weight scalar).
// ===========================================================================
__global__ void __launch_bounds__(256) k_rssm(
    const float* __restrict__ noise_p, const float* __restrict__ noise_o,
    const float* __restrict__ w_inp,  const float* __restrict__ w_gru,
    const float* __restrict__ b_gru_g,
    const float* __restrict__ w_img,  const float* __restrict__ b_img_g,
    const float* __restrict__ w_obsd,   // w_obs_out (rows 0..199 = deter part)
    const float* __restrict__ w_ims,  const float* __restrict__ b_ims_g,
    const float* __restrict__ w_obst, const float* __restrict__ b_obst_g,
    float* __restrict__ out) {
    const int tid = threadIdx.x;
    const int b0 = blockIdx.x * 4;

    __shared__ float stoch_s[4][32];
    __shared__ ulonglong2 x2s[Hc], d2s[Dc], dn2s[Dc], h2s[Hc], ho2s[Hc];
    __shared__ float stS[4][64], soS[4][64];
    __shared__ float bgru[600], bimg[Hc], bims[64], bobs[64];

    float* x_f  = reinterpret_cast<float*>(x2s);
    float* d_f  = reinterpret_cast<float*>(d2s);
    float* dn_f = reinterpret_cast<float*>(dn2s);
    float* h_f  = reinterpret_cast<float*>(h2s);
    float* ho_f = reinterpret_cast<float*>(ho2s);

    for (int i = tid; i < 600; i += 256) bgru[i] = b_gru_g[i];
    for (int i = tid; i < Hc; i += 256) bimg[i] = b_img_g[i];
    if (tid < 60) { bims[tid] = b_ims_g[tid]; bobs[tid] = b_obst_g[tid]; }
    for (int i = tid; i < 4 * Dc; i += 256) d_f[i] = 0.0f;
    if (tid < 128) reinterpret_cast<float*>(stoch_s)[tid] = 0.0f;
    __syncthreads();

    for (int t = 0; t < Tc; t++) {
        // ---- phase 1: x = elu(stoch @ Wis + pre_inp[t]) ----
        if (tid < Hc) {
            int j = tid;
            const float* pi = g_pre_inp + ((size_t)t * Bc + b0) * Hc + j;
            float a0 = pi[0], a1 = pi[Hc], a2 = pi[2 * Hc], a3 = pi[3 * Hc];
#pragma unroll
            for (int k = 0; k < Sc; k++) {
                float w = w_inp[k * Hc + j];
                a0 = fmaf(stoch_s[0][k], w, a0);
                a1 = fmaf(stoch_s[1][k], w, a1);
                a2 = fmaf(stoch_s[2][k], w, a2);
                a3 = fmaf(stoch_s[3][k], w, a3);
            }
            x_f[4 * j + 0] = eluf(a0); x_f[4 * j + 1] = eluf(a1);
            x_f[4 * j + 2] = eluf(a2); x_f[4 * j + 3] = eluf(a3);
        }
        __syncthreads();

        // ---- phase 2: GRU (thread j owns deter column j, all 3 gates, 4 rows)
        if (tid < Dc) {
            int j = tid;
            ull aR0 = 0, aR1 = 0, aC0 = 0, aC1 = 0, aU0 = 0, aU1 = 0;
            const ull* xp = reinterpret_cast<const ull*>(x2s);
            const ull* dp = reinterpret_cast<const ull*>(d2s);
#pragma unroll 4
            for (int k = 0; k < Hc; k++) {
                const float* wr = w_gru + k * 600 + j;
                ull wR = dup2(wr[0]), wC = dup2(wr[200]), wU = dup2(wr[400]);
                ull lo = xp[2 * k], hi = xp[2 * k + 1];
                fma2(aR0, lo, wR); fma2(aR1, hi, wR);
                fma2(aC0, lo, wC); fma2(aC1, hi, wC);
                fma2(aU0, lo, wU); fma2(aU1, hi, wU);
            }
#pragma unroll 4
            for (int k = 0; k < Dc; k++) {
                const float* wr = w_gru + (Hc + k) * 600 + j;
                ull wR = dup2(wr[0]), wC = dup2(wr[200]), wU = dup2(wr[400]);
                ull lo = dp[2 * k], hi = dp[2 * k + 1];
                fma2(aR0, lo, wR); fma2(aR1, hi, wR);
                fma2(aC0, lo, wC); fma2(aC1, hi, wC);
                fma2(aU0, lo, wU); fma2(aU1, hi, wU);
            }
            float2 Ra = up2(aR0), Rb = up2(aR1);
            float2 Ca = up2(aC0), Cb = up2(aC1);
            float2 Ua = up2(aU0), Ub = up2(aU1);
            float R[4] = {Ra.x, Ra.y, Rb.x, Rb.y};
            float C[4] = {Ca.x, Ca.y, Cb.x, Cb.y};
            float U[4] = {Ua.x, Ua.y, Ub.x, Ub.y};
            float bR = bgru[j], bC = bgru[200 + j], bU = bgru[400 + j];
#pragma unroll
            for (int r = 0; r < 4; r++) {
                float reset = sigm(R[r] + bR);
                float cand  = tanhf(reset * (C[r] + bC));
                float upd   = sigm(U[r] + bU - 1.0f);
                float dprev = d_f[4 * j + r];
                dn_f[4 * j + r] = upd * cand + (1.0f - upd) * dprev;
            }
        }
        __syncthreads();

        // ---- phase 3: h = elu(dn@Wimg+b), ho = elu(dn@Wobsd + pre_obs[t]) ----
        for (int cc = tid; cc < 400; cc += 256) {
            const ull* dnp = reinterpret_cast<const ull*>(dn2s);
            int j; const float* W; ull a0, a1;
            if (cc < 200) {
                j = cc;
                float bv = bimg[j];
                a0 = dup2(bv); a1 = a0;
                W = w_img + j;
            } else {
                j = cc - 200;
                const float* po = g_pre_obs + ((size_t)t * Bc + b0) * Hc + j;
                a0 = pk2(po[0], po[Hc]);
                a1 = pk2(po[2 * Hc], po[3 * Hc]);
                W = w_obsd + j;
            }
#pragma unroll 4
            for (int k = 0; k < Dc; k++) {
                ull wd = dup2(W[(size_t)k * Hc]);
                fma2(a0, dnp[2 * k], wd);
                fma2(a1, dnp[2 * k + 1], wd);
            }
            float2 v0 = up2(a0), v1 = up2(a1);
            float* dst = (cc < 200) ? h_f : ho_f;
            dst[4 * j + 0] = eluf(v0.x); dst[4 * j + 1] = eluf(v0.y);
            dst[4 * j + 2] = eluf(v1.x); dst[4 * j + 3] = eluf(v1.y);
        }
        __syncthreads();

        // ---- phase 4: stats st = h@Wims+b, so = ho@Wobst+b ----
        if (tid < 120) {
            bool post = (tid >= 60);
            int col = post ? tid - 60 : tid;
            const ull* src = post ? reinterpret_cast<const ull*>(ho2s)
                                  : reinterpret_cast<const ull*>(h2s);
            const float* W = post ? w_obst : w_ims;
            float bv = post ? bobs[col] : bims[col];
            ull a0 = dup2(bv), a1 = a0;
#pragma unroll 4
            for (int k = 0; k < Hc; k++) {
                ull wd = dup2(W[k * 60 + col]);
                fma2(a0, src[2 * k], wd);
                fma2(a1, src[2 * k + 1], wd);
            }
            float2 v0 = up2(a0), v1 = up2(a1);
            float* dst = post ? &soS[0][0] : &stS[0][0];
            dst[0 * 64 + col] = v0.x; dst[1 * 64 + col] = v0.y;
            dst[2 * 64 + col] = v1.x; dst[3 * 64 + col] = v1.y;
        }
        __syncthreads();

        // ---- phase 5: distributions, outputs, carry update ----
        if (tid < 120) {
            int r = tid / 30, k = tid - r * 30;
            int b = b0 + r;
            float om  = soS[r][k];
            float osv = softplusf(soS[r][30 + k]) + 0.1f;
            float ost = fmaf(osv, noise_o[((size_t)t * Bc + b) * Sc + k], om);
            float pm  = stS[r][k];
            float psv = softplusf(stS[r][30 + k]) + 0.1f;
            float pst = fmaf(psv, noise_p[((size_t)t * Bc + b) * Sc + k], pm);
            size_t base = ((size_t)b * Tc + t) * OUTC;
            out[base + k]       = om;
            out[base + 30 + k]  = osv;
            out[base + 60 + k]  = ost;
            out[base + 90 + k]  = pm;
            out[base + 120 + k] = psv;
            out[base + 150 + k] = pst;
            stoch_s[r][k] = ost;    // posterior sample is next stoch
        }
        for (int i2 = tid; i2 < 4 * Dc; i2 += 256) {
            int r = i2 / Dc; int j = i2 - r * Dc;
            float dv = dn_f[4 * j + r];
            out[((size_t)(b0 + r) * Tc + t) * OUTC + 180 + j] = dv;
            d_f[4 * j + r] = dv;    // deter <- deter_new
        }
        __syncthreads();
    }
}

// ===========================================================================
extern "C" void kernel_launch(void* const* d_in, const int* in_sizes, int n_in,
                              void* d_out, int out_size) {
    const float* embed       = (const float*)d_in[0];
    const float* action      = (const float*)d_in[1];
    const float* context     = (const float*)d_in[2];
    const float* noise_prior = (const float*)d_in[3];
    const float* noise_post  = (const float*)d_in[4];
    const float* w_inp       = (const float*)d_in[5];
    const float* b_inp       = (const float*)d_in[6];
    const float* w_gru       = (const float*)d_in[7];
    const float* b_gru       = (const float*)d_in[8];
    const float* w_img_out   = (const float*)d_in[9];
    const float* b_img_out   = (const float*)d_in[10];
    const float* w_obs_out   = (const float*)d_in[11];
    const float* b_obs_out   = (const float*)d_in[12];
    const float* w_ims_stat  = (const float*)d_in[13];
    const float* b_ims_stat  = (const float*)d_in[14];
    const float* w_obs_stat  = (const float*)d_in[15];
    const float* b_obs_stat  = (const float*)d_in[16];
    float* out = (float*)d_out;

    k_pre_inp<<<dim3(Bc * Tc / 64, 4), 128>>>(context, action, w_inp, b_inp);
    k_pre_obs<<<dim3(Bc * Tc / 64, 4), 128>>>(embed, w_obs_out, b_obs_out);
    k_rssm<<<Bc / 4, 256>>>(noise_prior, noise_post, w_inp, w_gru, b_gru,
                            w_img_out, b_img_out, w_obs_out,
                            w_ims_stat, b_ims_stat, w_obs_stat, b_obs_stat, out);
}

// round 4
// speedup vs baseline: 2.0002x; 2.0002x over previous
#include <cuda_runtime.h>
#include <cstdint>

// ---------------------------------------------------------------------------
// RSSM observe scan, GB300 — round 3.
//   k_pre_inp / k_pre_obs : unchanged (hoisted time-parallel GEMMs)
//   k_rssm v2 : 64 CTAs x 8 batch rows, 640 threads.
//     Column-parallel GRU (600 threads x 1 gate-column, K=400 fused x||d),
//     raw preacts staged in smem, dense coverage in all phases.
// ---------------------------------------------------------------------------

#define Bc 512
#define Tc 64
#define Ec 1024
#define Ac 32
#define Sc 30
#define Dc 200
#define Hc 200
#define SSc 230
#define OUTC 380
#define Rr 8            // batch rows per CTA
#define NCTA (Bc / Rr)  // 64

typedef unsigned long long ull;

__device__ float g_pre_inp[Tc * Bc * Hc];
__device__ float g_pre_obs[Tc * Bc * Hc];

// ---- packed f32x2 helpers -------------------------------------------------
__device__ __forceinline__ ull pk2(float a, float b) {
    ull r; asm("mov.b64 %0, {%1, %2};" : "=l"(r) : "f"(a), "f"(b)); return r;
}
__device__ __forceinline__ ull dup2(float a) {
    ull r; asm("mov.b64 %0, {%1, %1};" : "=l"(r) : "f"(a)); return r;
}
__device__ __forceinline__ float2 up2(ull v) {
    float x, y; asm("mov.b64 {%0, %1}, %2;" : "=f"(x), "=f"(y) : "l"(v));
    return make_float2(x, y);
}
__device__ __forceinline__ void fma2(ull& acc, ull a, ull b) {
    asm("fma.rn.f32x2 %0, %1, %2, %0;" : "+l"(acc) : "l"(a), "l"(b));
}

__device__ __forceinline__ float sigm(float x) { return 1.0f / (1.0f + __expf(-x)); }
__device__ __forceinline__ float eluf(float x) { return x > 0.0f ? x : expm1f(x); }
__device__ __forceinline__ float softplusf(float x) {
    return x > 15.0f ? x : log1pf(__expf(x));
}

// ===========================================================================
// k_pre_obs: [32768, 1024] x [1024, 200]  (weight rows 200..1223 of w_obs_out)
// ===========================================================================
__global__ void __launch_bounds__(128) k_pre_obs(const float* __restrict__ embed,
                                                 const float* __restrict__ w_obs,
                                                 const float* __restrict__ b_obs) {
    __shared__ __align__(8) float As[16][66];
    const int tid = threadIdx.x;
    const int jp = tid & 31, rg = tid >> 5;
    const int row0 = blockIdx.x * 64;
    const int j0 = blockIdx.y * 64 + jp * 2;
    const bool act = (j0 < Hc);
    const int rbase = rg * 16;

    ull acc[16];
#pragma unroll
    for (int i = 0; i < 16; i++) acc[i] = 0ull;

    for (int k0 = 0; k0 < Ec; k0 += 16) {
#pragma unroll
        for (int i = 0; i < 8; i++) {
            int lin = tid + i * 128;
            int kk = lin & 15, r = lin >> 4;
            int rowg = row0 + r;
            int tt = rowg >> 9, bb = rowg & 511;
            As[kk][r] = embed[(size_t)(bb * Tc + tt) * Ec + k0 + kk];
        }
        __syncthreads();
        if (act) {
#pragma unroll
            for (int kk = 0; kk < 16; kk++) {
                float2 w = *reinterpret_cast<const float2*>(
                    w_obs + (size_t)(Dc + k0 + kk) * Hc + j0);
                ull wx = dup2(w.x), wy = dup2(w.y);
                const ull* ap = reinterpret_cast<const ull*>(&As[kk][rbase]);
#pragma unroll
                for (int p = 0; p < 8; p++) {
                    ull a = ap[p];
                    fma2(acc[2 * p], a, wx);
                    fma2(acc[2 * p + 1], a, wy);
                }
            }
        }
        __syncthreads();
    }
    if (act) {
        float bx = b_obs[j0], by = b_obs[j0 + 1];
#pragma unroll
        for (int p = 0; p < 8; p++) {
            float2 va = up2(acc[2 * p]), vb = up2(acc[2 * p + 1]);
            int r = row0 + rbase + 2 * p;
            *reinterpret_cast<float2*>(g_pre_obs + (size_t)r * Hc + j0) =
                make_float2(va.x + bx, vb.x + by);
            *reinterpret_cast<float2*>(g_pre_obs + (size_t)(r + 1) * Hc + j0) =
                make_float2(va.y + bx, vb.y + by);
        }
    }
}

// ===========================================================================
// k_pre_inp: [32768, 262] x [262, 200]
// ===========================================================================
__global__ void __launch_bounds__(128) k_pre_inp(const float* __restrict__ ctx,
                                                 const float* __restrict__ actn,
                                                 const float* __restrict__ w_inp,
                                                 const float* __restrict__ b_inp) {
    __shared__ __align__(8) float As[16][66];
    const int tid = threadIdx.x;
    const int jp = tid & 31, rg = tid >> 5;
    const int row0 = blockIdx.x * 64;
    const int j0 = blockIdx.y * 64 + jp * 2;
    const bool act = (j0 < Hc);
    const int rbase = rg * 16;

    ull acc[16];
#pragma unroll
    for (int i = 0; i < 16; i++) acc[i] = 0ull;

    for (int k0 = 0; k0 < 272; k0 += 16) {
#pragma unroll
        for (int i = 0; i < 8; i++) {
            int lin = tid + i * 128;
            int kk = lin & 15, r = lin >> 4;
            int rowg = row0 + r;
            int tt = rowg >> 9, bb = rowg & 511;
            int k = k0 + kk;
            float v = 0.0f;
            if (k < SSc)            v = ctx[(size_t)(bb * Tc + tt) * SSc + k];
            else if (k < SSc + Ac)  v = actn[(size_t)(bb * Tc + tt) * Ac + (k - SSc)];
            As[kk][r] = v;
        }
        __syncthreads();
        if (act) {
#pragma unroll
            for (int kk = 0; kk < 16; kk++) {
                int kw = (k0 + kk < SSc + Ac) ? (k0 + kk) : (SSc + Ac - 1);
                float2 w = *reinterpret_cast<const float2*>(
                    w_inp + (size_t)(Sc + kw) * Hc + j0);
                ull wx = dup2(w.x), wy = dup2(w.y);
                const ull* ap = reinterpret_cast<const ull*>(&As[kk][rbase]);
#pragma unroll
                for (int p = 0; p < 8; p++) {
                    ull a = ap[p];
                    fma2(acc[2 * p], a, wx);
                    fma2(acc[2 * p + 1], a, wy);
                }
            }
        }
        __syncthreads();
    }
    if (act) {
        float bx = b_inp[j0], by = b_inp[j0 + 1];
#pragma unroll
        for (int p = 0; p < 8; p++) {
            float2 va = up2(acc[2 * p]), vb = up2(acc[2 * p + 1]);
            int r = row0 + rbase + 2 * p;
            *reinterpret_cast<float2*>(g_pre_inp + (size_t)r * Hc + j0) =
                make_float2(va.x + bx, vb.x + by);
            *reinterpret_cast<float2*>(g_pre_inp + (size_t)(r + 1) * Hc + j0) =
                make_float2(va.y + bx, vb.y + by);
        }
    }
}

// ===========================================================================
// k_rssm v2: 64 CTAs x 8 rows, 640 threads.
// smem activation layout: float[col][row] with row fastest (8 rows = 4 ull
// pairs = 2 ulonglong2), so broadcast LDS.128 feeds f32x2 FMA directly.
// ===========================================================================
__global__ void __launch_bounds__(640, 1) k_rssm(
    const float* __restrict__ noise_p, const float* __restrict__ noise_o,
    const float* __restrict__ w_inp,  const float* __restrict__ w_gru,
    const float* __restrict__ b_gru_g,
    const float* __restrict__ w_img,  const float* __restrict__ b_img_g,
    const float* __restrict__ w_obsd,   // w_obs_out rows 0..199 (deter part)
    const float* __restrict__ w_ims,  const float* __restrict__ b_ims_g,
    const float* __restrict__ w_obst, const float* __restrict__ b_obst_g,
    float* __restrict__ out) {
    const int tid = threadIdx.x;
    const int b0 = blockIdx.x * Rr;

    // xd: [400][8]  (k<200 -> x, k>=200 -> d)
    __shared__ __align__(16) float xd_f[400 * Rr];       // 12.8 KB
    __shared__ __align__(16) float dn_f[Dc * Rr];        //  6.4 KB
    // union region: praw[600][8] (19.2 KB) -> later h[200][8], ho[200][8],
    // stS[8][64], soS[8][64]
    __shared__ __align__(16) float un_f[600 * Rr];       // 19.2 KB
    __shared__ __align__(16) float st_f[32 * Rr];        // stoch [k][r]
    __shared__ float bgru[600], bimg[Hc], bims[64], bobs[64];

    ull* xd_u = reinterpret_cast<ull*>(xd_f);
    ulonglong2* xd_u2 = reinterpret_cast<ulonglong2*>(xd_f);
    ull* dn_u = reinterpret_cast<ull*>(dn_f);
    ulonglong2* dn_u2 = reinterpret_cast<ulonglong2*>(dn_f);
    ull* st_u = reinterpret_cast<ull*>(st_f);
    ull* praw_u = reinterpret_cast<ull*>(un_f);
    float* h_f = un_f;                      // [200][8]
    float* ho_f = un_f + 200 * Rr;          // [200][8]
    ull* h_u = reinterpret_cast<ull*>(h_f);
    ull* ho_u = reinterpret_cast<ull*>(ho_f);
    float* stS = un_f + 400 * Rr;           // [8][64]
    float* soS = stS + 8 * 64;              // [8][64]

    for (int i = tid; i < 600; i += 640) bgru[i] = b_gru_g[i];
    for (int i = tid; i < Hc; i += 640) bimg[i] = b_img_g[i];
    if (tid < 60) { bims[tid] = b_ims_g[tid]; bobs[tid] = b_obst_g[tid]; }
    for (int i = tid; i < Dc * Rr; i += 640) xd_f[200 * Rr + i] = 0.0f;  // d = 0
    for (int i = tid; i < 32 * Rr; i += 640) st_f[i] = 0.0f;             // stoch = 0
    __syncthreads();

    for (int t = 0; t < Tc; t++) {
        // ---- phase 1: x = elu(stoch @ Wis[30x200] + pre_inp[t]) ----
        // 400 threads: (col j, row-half h) -> pairs 2h, 2h+1
        if (tid < 400) {
            const int j = tid >> 1, hh = tid & 1;
            const float* pi = g_pre_inp + ((size_t)t * Bc + b0) * Hc + j;
            ull a0 = pk2(pi[(4 * hh + 0) * Hc], pi[(4 * hh + 1) * Hc]);
            ull a1 = pk2(pi[(4 * hh + 2) * Hc], pi[(4 * hh + 3) * Hc]);
#pragma unroll
            for (int k = 0; k < Sc; k++) {
                ull wd = dup2(w_inp[k * Hc + j]);
                fma2(a0, st_u[k * 4 + 2 * hh], wd);
                fma2(a1, st_u[k * 4 + 2 * hh + 1], wd);
            }
            float2 v0 = up2(a0), v1 = up2(a1);
            float* xo = &xd_f[j * Rr + 4 * hh];
            xo[0] = eluf(v0.x); xo[1] = eluf(v0.y);
            xo[2] = eluf(v1.x); xo[3] = eluf(v1.y);
        }
        __syncthreads();

        // ---- phase 2: GRU pre-activations, column-parallel ----
        // 600 threads: thread c owns gate-column c of [400 x 600]
        if (tid < 600) {
            const int c = tid;
            ull A0 = 0, A1 = 0, A2 = 0, A3 = 0;
            const float* W = w_gru + c;
#pragma unroll 8
            for (int k = 0; k < 400; k++) {
                ull wd = dup2(W[(size_t)k * 600]);
                ulonglong2 v0 = xd_u2[k * 2], v1 = xd_u2[k * 2 + 1];
                fma2(A0, v0.x, wd); fma2(A1, v0.y, wd);
                fma2(A2, v1.x, wd); fma2(A3, v1.y, wd);
            }
            praw_u[c * 4 + 0] = A0; praw_u[c * 4 + 1] = A1;
            praw_u[c * 4 + 2] = A2; praw_u[c * 4 + 3] = A3;
        }
        __syncthreads();

        // ---- combine: gates -> deter_new ----
        if (tid < Dc) {
            const int j = tid;
            const float bR = bgru[j], bC = bgru[200 + j], bU = bgru[400 + j];
#pragma unroll
            for (int p = 0; p < 4; p++) {
                float2 Rv = up2(praw_u[j * 4 + p]);
                float2 Cv = up2(praw_u[(200 + j) * 4 + p]);
                float2 Uv = up2(praw_u[(400 + j) * 4 + p]);
                float R[2] = {Rv.x, Rv.y}, C[2] = {Cv.x, Cv.y}, U[2] = {Uv.x, Uv.y};
#pragma unroll
                for (int q = 0; q < 2; q++) {
                    int r = 2 * p + q;
                    float reset = sigm(R[q] + bR);
                    float cand  = tanhf(reset * (C[q] + bC));
                    float upd   = sigm(U[q] + bU - 1.0f);
                    float dprev = xd_f[(200 + j) * Rr + r];
                    dn_f[j * Rr + r] = upd * cand + (1.0f - upd) * dprev;
                }
            }
        }
        __syncthreads();

        // ---- phase 3: h = elu(dn@Wimg+b); ho = elu(dn@Wobsd + pre_obs[t]) ----
        // 400 threads: one output column each, K = 200
        if (tid < 400) {
            const int col = tid;
            const float* W;
            ull A0, A1, A2, A3;
            if (col < 200) {
                W = w_img + col;
                A0 = dup2(bimg[col]); A1 = A0; A2 = A0; A3 = A0;
            } else {
                const int jj = col - 200;
                W = w_obsd + jj;
                const float* po = g_pre_obs + ((size_t)t * Bc + b0) * Hc + jj;
                A0 = pk2(po[0 * Hc], po[1 * Hc]);
                A1 = pk2(po[2 * Hc], po[3 * Hc]);
                A2 = pk2(po[4 * Hc], po[5 * Hc]);
                A3 = pk2(po[6 * Hc], po[7 * Hc]);
            }
#pragma unroll 8
            for (int k = 0; k < Dc; k++) {
                ull wd = dup2(W[(size_t)k * Hc]);
                ulonglong2 v0 = dn_u2[k * 2], v1 = dn_u2[k * 2 + 1];
                fma2(A0, v0.x, wd); fma2(A1, v0.y, wd);
                fma2(A2, v1.x, wd); fma2(A3, v1.y, wd);
            }
            // NOTE: h/ho overlay praw storage; praw is dead now, but all
            // reads of praw happened before the previous __syncthreads().
            float2 v0 = up2(A0), v1 = up2(A1), v2 = up2(A2), v3 = up2(A3);
            float* dst = (col < 200) ? &h_f[col * Rr] : &ho_f[(col - 200) * Rr];
            dst[0] = eluf(v0.x); dst[1] = eluf(v0.y);
            dst[2] = eluf(v1.x); dst[3] = eluf(v1.y);
            dst[4] = eluf(v2.x); dst[5] = eluf(v2.y);
            dst[6] = eluf(v3.x); dst[7] = eluf(v3.y);
        }
        __syncthreads();

        // ---- phase 4: stats (st = h@Wims+b, so = ho@Wobst+b) ----
        // 480 threads: (column-group 0..119, row-pair 0..3)
        if (tid < 480) {
            const int p = tid & 3, cg = tid >> 2;
            const bool post = (cg >= 60);
            const int col = post ? cg - 60 : cg;
            const float* W = post ? w_obst : w_ims;
            const ull* src = post ? ho_u : h_u;
            ull A = dup2(post ? bobs[col] : bims[col]);
#pragma unroll 8
            for (int k = 0; k < Hc; k++) {
                fma2(A, src[k * 4 + p], dup2(W[k * 60 + col]));
            }
            float2 v = up2(A);
            float* dst = post ? soS : stS;
            dst[(2 * p) * 64 + col] = v.x;
            dst[(2 * p + 1) * 64 + col] = v.y;
        }
        __syncthreads();

        // ---- phase 5: sample, outputs, carry update ----
        if (tid < Rr * Sc) {
            const int r = tid / Sc, k = tid - r * Sc;
            const int b = b0 + r;
            float om  = soS[r * 64 + k];
            float osv = softplusf(soS[r * 64 + 30 + k]) + 0.1f;
            float ost = fmaf(osv, noise_o[((size_t)t * Bc + b) * Sc + k], om);
            float pm  = stS[r * 64 + k];
            float psv = softplusf(stS[r * 64 + 30 + k]) + 0.1f;
            float pst = fmaf(psv, noise_p[((size_t)t * Bc + b) * Sc + k], pm);
            size_t base = ((size_t)b * Tc + t) * OUTC;
            out[base + k]       = om;
            out[base + 30 + k]  = osv;
            out[base + 60 + k]  = ost;
            out[base + 90 + k]  = pm;
            out[base + 120 + k] = psv;
            out[base + 150 + k] = pst;
            st_f[k * Rr + r] = ost;          // next stoch = posterior sample
        }
        for (int i = tid; i < Dc * Rr; i += 640) {
            const int r = i / Dc, j = i - r * Dc;   // coalesced over j
            const float dv = dn_f[j * Rr + r];
            out[((size_t)(b0 + r) * Tc + t) * OUTC + 180 + j] = dv;
            xd_f[(200 + j) * Rr + r] = dv;          // d <- deter_new
        }
        __syncthreads();
    }
}

// ===========================================================================
extern "C" void kernel_launch(void* const* d_in, const int* in_sizes, int n_in,
                              void* d_out, int out_size) {
    const float* embed       = (const float*)d_in[0];
    const float* action      = (const float*)d_in[1];
    const float* context     = (const float*)d_in[2];
    const float* noise_prior = (const float*)d_in[3];
    const float* noise_post  = (const float*)d_in[4];
    const float* w_inp       = (const float*)d_in[5];
    const float* b_inp       = (const float*)d_in[6];
    const float* w_gru       = (const float*)d_in[7];
    const float* b_gru       = (const float*)d_in[8];
    const float* w_img_out   = (const float*)d_in[9];
    const float* b_img_out   = (const float*)d_in[10];
    const float* w_obs_out   = (const float*)d_in[11];
    const float* b_obs_out   = (const float*)d_in[12];
    const float* w_ims_stat  = (const float*)d_in[13];
    const float* b_ims_stat  = (const float*)d_in[14];
    const float* w_obs_stat  = (const float*)d_in[15];
    const float* b_obs_stat  = (const float*)d_in[16];
    float* out = (float*)d_out;

    k_pre_inp<<<dim3(Bc * Tc / 64, 4), 128>>>(context, action, w_inp, b_inp);
    k_pre_obs<<<dim3(Bc * Tc / 64, 4), 128>>>(embed, w_obs_out, b_obs_out);
    k_rssm<<<NCTA, 640>>>(noise_prior, noise_post, w_inp, w_gru, b_gru,
                          w_img_out, b_img_out, w_obs_out,
                          w_ims_stat, b_ims_stat, w_obs_stat, b_obs_stat, out);
}